// round 2
// baseline (speedup 1.0000x reference)
#include <cuda_runtime.h>
#include <stdint.h>

#define NUM_CLASSES 32000
#define C4 (NUM_CLASSES / 4)
#define ALPHA 0.95f
#define THREADS 512
#define SMEM_BYTES (NUM_CLASSES * 4)   // 128000 B = 125 KB

// Flag: 1 if labels buffer is int64, 0 if int32. Set by detect_kernel.
__device__ int g_lab_is_64 = 0;

// Decide label dtype by interpreting the first n/2 entries as uint64.
// If truly int64: all n/2 values are real labels < 32000 -> flag=1.
// If truly int32: a uint64 read pairs two int32 labels and is < 32000 only if
// the odd-position label is exactly 0; all-pairs probability ~(1/32000)^2048 ~ 0.
__global__ void detect_kernel(const unsigned long long* __restrict__ labels, int n_half) {
    __shared__ int bad;
    if (threadIdx.x == 0) bad = 0;
    __syncthreads();
    int local_bad = 0;
    for (int i = threadIdx.x; i < n_half; i += blockDim.x) {
        if (labels[i] >= (unsigned long long)NUM_CLASSES) local_bad = 1;
    }
    if (local_bad) bad = 1;
    __syncthreads();
    if (threadIdx.x == 0) g_lab_is_64 = (bad == 0) ? 1 : 0;
}

__global__ __launch_bounds__(THREADS, 1)
void distill_kernel(const float* __restrict__ x,
                    const void*  __restrict__ labels,
                    float*       __restrict__ out) {
    extern __shared__ float srow[];                       // one full row, 125 KB
    float4* __restrict__ sr4 = reinterpret_cast<float4*>(srow);

    const int row = blockIdx.x;
    const int tid = threadIdx.x;

    const float4* __restrict__ xr   = reinterpret_cast<const float4*>(x + (size_t)row * NUM_CLASSES);
    float4*       __restrict__ orow = reinterpret_cast<float4*>(out + (size_t)row * NUM_CLASSES);

    // Label (dtype chosen at runtime via detection flag) — issue early.
    int lab;
    if (g_lab_is_64) lab = (int)(((const long long*)labels)[row]);
    else             lab = ((const int*)labels)[row];

    // ---- Phase 1: stream row into SMEM (single DRAM read), accumulate sum ----
    float sum = 0.0f;
    #pragma unroll 4
    for (int i = tid; i < C4; i += THREADS) {
        float4 v = __ldcs(&xr[i]);                        // streaming: no reuse from L2 needed
        sr4[i] = v;
        sum += (v.x + v.y) + (v.z + v.w);
    }

    // Block reduce: warp shuffle, then first warp folds the 16 partials.
    __shared__ float warp_sums[THREADS / 32];
    __shared__ float s_S;
    #pragma unroll
    for (int off = 16; off > 0; off >>= 1)
        sum += __shfl_down_sync(0xffffffffu, sum, off);
    const int lane = tid & 31;
    const int wid  = tid >> 5;
    if (lane == 0) warp_sums[wid] = sum;
    __syncthreads();
    if (wid == 0) {
        float v = (lane < THREADS / 32) ? warp_sums[lane] : 0.0f;
        #pragma unroll
        for (int off = 8; off > 0; off >>= 1)
            v += __shfl_down_sync(0xffffffffu, v, off);
        if (lane == 0) s_S = v;
    }
    __syncthreads();

    const float S = s_S;
    const float t = srow[lab];                            // from SMEM — no extra global load
    const float s = ALPHA / (1.0f + S - 2.0f * t);
    const float corr = 1.0f - s * S;

    const int lab4 = lab >> 2;
    const int labc = lab & 3;

    // ---- Phase 2: scale from SMEM + fused label correction, streaming stores ----
    #pragma unroll 4
    for (int i = tid; i < C4; i += THREADS) {
        float4 v = sr4[i];
        float4 o;
        o.x = s * v.x;
        o.y = s * v.y;
        o.z = s * v.z;
        o.w = s * v.w;
        if (i == lab4) {
            reinterpret_cast<float*>(&o)[labc] += corr;
        }
        __stcs(&orow[i], o);                              // streaming store: don't pollute L2
    }
}

extern "C" void kernel_launch(void* const* d_in, const int* in_sizes, int n_in,
                              void* d_out, int out_size) {
    const float* teacher_logits = (const float*)d_in[0];
    const void*  true_labels    = d_in[1];
    float* out = (float*)d_out;

    const int batch = in_sizes[1];   // 4096 rows (label count)

    cudaFuncSetAttribute(distill_kernel,
                         cudaFuncAttributeMaxDynamicSharedMemorySize, SMEM_BYTES);

    detect_kernel<<<1, 256>>>((const unsigned long long*)true_labels, batch / 2);
    distill_kernel<<<batch, THREADS, SMEM_BYTES>>>(teacher_logits, true_labels, out);
}

// round 3
// speedup vs baseline: 1.2730x; 1.2730x over previous
#include <cuda_runtime.h>
#include <stdint.h>

#define NUM_CLASSES 32000
#define C4 (NUM_CLASSES / 4)     // 8000 float4 slots per row
#define ALPHA 0.95f
#define THREADS 1024
#define KITEMS 8                 // 8 * 1024 = 8192 >= 8000

// Flag: 1 if labels buffer is int64, 0 if int32. Set by detect_kernel.
__device__ int g_lab_is_64 = 0;

// Decide label dtype by interpreting the first n/2 entries as uint64.
// If truly int64: all n/2 values are real labels < 32000 -> flag=1.
// If truly int32: a uint64 read pairs two int32 labels and is < 32000 only if
// the odd-position label is exactly 0; all-pairs probability ~(1/32000)^2048 ~ 0.
__global__ void detect_kernel(const unsigned long long* __restrict__ labels, int n_half) {
    __shared__ int bad;
    if (threadIdx.x == 0) bad = 0;
    __syncthreads();
    int local_bad = 0;
    for (int i = threadIdx.x; i < n_half; i += blockDim.x) {
        if (labels[i] >= (unsigned long long)NUM_CLASSES) local_bad = 1;
    }
    if (local_bad) bad = 1;
    __syncthreads();
    if (threadIdx.x == 0) g_lab_is_64 = (bad == 0) ? 1 : 0;
}

__global__ __launch_bounds__(THREADS, 1)
void distill_kernel(const float* __restrict__ x,
                    const void*  __restrict__ labels,
                    float*       __restrict__ out) {
    const int row = blockIdx.x;
    const int tid = threadIdx.x;

    const float4* __restrict__ xr   = reinterpret_cast<const float4*>(x + (size_t)row * NUM_CLASSES);
    float4*       __restrict__ orow = reinterpret_cast<float4*>(out + (size_t)row * NUM_CLASSES);

    // Label + t: issue the two scalar loads immediately so their latency is
    // hidden under the bulk row loads.
    int lab;
    if (g_lab_is_64) lab = (int)(((const long long*)labels)[row]);
    else             lab = ((const int*)labels)[row];
    const float t = __ldg(x + (size_t)row * NUM_CLASSES + lab);

    // ---- Phase 1: load 8 float4 per thread into registers (deep MLP) ----
    float4 v[KITEMS];
    float sum = 0.0f;
    #pragma unroll
    for (int k = 0; k < KITEMS; k++) {
        const int i = tid + k * THREADS;
        if (k < KITEMS - 1 || i < C4) {             // only k=7 needs the predicate
            v[k] = __ldcs(&xr[i]);
            sum += (v[k].x + v[k].y) + (v[k].z + v[k].w);
        }
    }

    // Block reduce: warp shuffle, then first warp folds the 32 partials.
    __shared__ float warp_sums[THREADS / 32];
    __shared__ float s_S;
    #pragma unroll
    for (int off = 16; off > 0; off >>= 1)
        sum += __shfl_down_sync(0xffffffffu, sum, off);
    const int lane = tid & 31;
    const int wid  = tid >> 5;
    if (lane == 0) warp_sums[wid] = sum;
    __syncthreads();
    if (wid == 0) {
        float r = (lane < THREADS / 32) ? warp_sums[lane] : 0.0f;
        #pragma unroll
        for (int off = 16; off > 0; off >>= 1)
            r += __shfl_down_sync(0xffffffffu, r, off);
        if (lane == 0) s_S = r;
    }
    __syncthreads();

    const float S = s_S;
    const float s = ALPHA / (1.0f + S - 2.0f * t);
    const float corr = 1.0f - s * S;

    const int lab4 = lab >> 2;
    const int labc = lab & 3;

    // ---- Phase 2: scale registers + fused label correction, streaming stores ----
    #pragma unroll
    for (int k = 0; k < KITEMS; k++) {
        const int i = tid + k * THREADS;
        if (k < KITEMS - 1 || i < C4) {
            float4 o;
            o.x = s * v[k].x;
            o.y = s * v[k].y;
            o.z = s * v[k].z;
            o.w = s * v[k].w;
            if (i == lab4) {
                reinterpret_cast<float*>(&o)[labc] += corr;
            }
            __stcs(&orow[i], o);
        }
    }
}

extern "C" void kernel_launch(void* const* d_in, const int* in_sizes, int n_in,
                              void* d_out, int out_size) {
    const float* teacher_logits = (const float*)d_in[0];
    const void*  true_labels    = d_in[1];
    float* out = (float*)d_out;

    const int batch = in_sizes[1];   // 4096 rows (label count)

    detect_kernel<<<1, 256>>>((const unsigned long long*)true_labels, batch / 2);
    distill_kernel<<<batch, THREADS>>>(teacher_logits, true_labels, out);
}

// round 4
// speedup vs baseline: 1.3757x; 1.0807x over previous
#include <cuda_runtime.h>
#include <stdint.h>

#define NUM_CLASSES 32000
#define C4 (NUM_CLASSES / 4)        // 8000 float4 slots per row
#define ALPHA 0.95f
#define THREADS 512
#define RITEMS 10                   // float4s per thread in registers
#define RSLOTS (RITEMS * THREADS)   // 5120 slots in regs
#define SSLOTS (C4 - RSLOTS)        // 2880 slots in smem
#define SITER  ((SSLOTS + THREADS - 1) / THREADS)   // 6 (last partial)
#define SMEM_STAGE_BYTES (SSLOTS * 16)              // 46080 B

// Flag: 1 if labels buffer is int64, 0 if int32. Set by detect_kernel.
__device__ int g_lab_is_64 = 0;

// Interpret the first 64 entries as uint64. If truly int64 they are labels
// < 32000 -> flag=1. If truly int32, each u64 pairs two labels and is < 32000
// only when the odd-position label is 0: P(all 32) ~ (1/32000)^32 ~ 0.
__global__ void detect_kernel(const unsigned long long* __restrict__ labels) {
    int bad = (labels[threadIdx.x] >= (unsigned long long)NUM_CLASSES) ? 1 : 0;
    #pragma unroll
    for (int off = 16; off > 0; off >>= 1)
        bad |= __shfl_down_sync(0xffffffffu, bad, off);
    bad |= __shfl_sync(0xffffffffu, bad, 0);   // broadcast combined (lanes 0..31 read two halves)
    if (threadIdx.x == 0) g_lab_is_64 = bad ? 0 : 1;
}

__global__ __launch_bounds__(THREADS, 2)
void distill_kernel(const float* __restrict__ x,
                    const void*  __restrict__ labels,
                    float*       __restrict__ out) {
    __shared__ float4 s4[SSLOTS];            // per-thread private staging (no barrier needed)

    const int row = blockIdx.x;
    const int tid = threadIdx.x;

    const float4* __restrict__ xr   = reinterpret_cast<const float4*>(x + (size_t)row * NUM_CLASSES);
    float4*       __restrict__ orow = reinterpret_cast<float4*>(out + (size_t)row * NUM_CLASSES);

    // Label + t: issue early so latency hides under the bulk loads.
    int lab;
    if (g_lab_is_64) lab = (int)(((const long long*)labels)[row]);
    else             lab = ((const int*)labels)[row];
    const float t = __ldg(x + (size_t)row * NUM_CLASSES + lab);

    // ---- Phase 1a: 10 float4/thread into registers (deep MLP) ----
    float4 v[RITEMS];
    float sum = 0.0f;
    #pragma unroll
    for (int k = 0; k < RITEMS; k++) {
        v[k] = __ldcs(&xr[tid + k * THREADS]);
        sum += (v[k].x + v[k].y) + (v[k].z + v[k].w);
    }
    // ---- Phase 1b: remaining 2880 float4 staged in smem (thread-private slots) ----
    #pragma unroll
    for (int k = 0; k < SITER; k++) {
        const int j = tid + k * THREADS;
        if (k < SITER - 1 || j < SSLOTS) {
            float4 w = __ldcs(&xr[RSLOTS + j]);
            s4[j] = w;
            sum += (w.x + w.y) + (w.z + w.w);
        }
    }

    // Block reduce across 16 warps.
    __shared__ float warp_sums[THREADS / 32];
    __shared__ float s_S;
    #pragma unroll
    for (int off = 16; off > 0; off >>= 1)
        sum += __shfl_down_sync(0xffffffffu, sum, off);
    const int lane = tid & 31;
    const int wid  = tid >> 5;
    if (lane == 0) warp_sums[wid] = sum;
    __syncthreads();
    if (wid == 0) {
        float r = (lane < THREADS / 32) ? warp_sums[lane] : 0.0f;
        #pragma unroll
        for (int off = 8; off > 0; off >>= 1)
            r += __shfl_down_sync(0xffffffffu, r, off);
        if (lane == 0) s_S = r;
    }
    __syncthreads();

    const float S = s_S;
    const float s = ALPHA / (1.0f + S - 2.0f * t);
    const float corr = 1.0f - s * S;

    const int lab4 = lab >> 2;
    const int labc = lab & 3;

    // ---- Phase 2a: scale registers, fused label correction, streaming stores ----
    #pragma unroll
    for (int k = 0; k < RITEMS; k++) {
        const int i = tid + k * THREADS;
        float4 o;
        o.x = s * v[k].x;
        o.y = s * v[k].y;
        o.z = s * v[k].z;
        o.w = s * v[k].w;
        if (i == lab4) reinterpret_cast<float*>(&o)[labc] += corr;
        __stcs(&orow[i], o);
    }
    // ---- Phase 2b: scale smem-staged part ----
    #pragma unroll
    for (int k = 0; k < SITER; k++) {
        const int j = tid + k * THREADS;
        if (k < SITER - 1 || j < SSLOTS) {
            float4 w = s4[j];
            const int i = RSLOTS + j;
            float4 o;
            o.x = s * w.x;
            o.y = s * w.y;
            o.z = s * w.z;
            o.w = s * w.w;
            if (i == lab4) reinterpret_cast<float*>(&o)[labc] += corr;
            __stcs(&orow[i], o);
        }
    }
}

extern "C" void kernel_launch(void* const* d_in, const int* in_sizes, int n_in,
                              void* d_out, int out_size) {
    const float* teacher_logits = (const float*)d_in[0];
    const void*  true_labels    = d_in[1];
    float* out = (float*)d_out;

    const int batch = in_sizes[1];   // 4096 rows (label count)

    detect_kernel<<<1, 64>>>((const unsigned long long*)true_labels);
    distill_kernel<<<batch, THREADS>>>(teacher_logits, true_labels, out);
}